// round 1
// baseline (speedup 1.0000x reference)
#include <cuda_runtime.h>
#include <math.h>

// Problem constants (fixed by the dataset)
#define MAXN 100000
#define MAXE 1600000

// Scratch (allocation-free rule: __device__ globals)
__device__ float g_h[(size_t)MAXN * 128];    // h = x @ W (per layer)
__device__ float g_agg[(size_t)MAXN * 128];  // aggregated layer-1 output
__device__ float g_g1[MAXE];                 // edge gates layer 1
__device__ float g_g2[MAXE];                 // edge gates layer 2
__device__ float g_d1[MAXN];                 // deg -> rsqrt(deg) layer 1
__device__ float g_d2[MAXN];                 // deg -> rsqrt(deg) layer 2

// ---------------------------------------------------------------------------
// deg init: self-loop weight 1.0
__global__ void init_deg_kernel(float* d1, float* d2, int n) {
    int i = blockIdx.x * blockDim.x + threadIdx.x;
    if (i < n) { d1[i] = 1.0f; d2[i] = 1.0f; }
}

// ---------------------------------------------------------------------------
// Edge gate MLPs for BOTH layers in one pass over edge_attr.
// g = sigmoid( relu(ea @ w1 + b1) @ w2 + b2 ), per edge.
// One thread per edge; weights in shared (uniform broadcast reads).
// Also accumulates weighted in-degree per target node.
__global__ void gate_kernel(
    const float* __restrict__ ea,
    const float* __restrict__ w1a, const float* __restrict__ b1a,
    const float* __restrict__ w2a, const float* __restrict__ b2a,
    const float* __restrict__ w1b, const float* __restrict__ b1b,
    const float* __restrict__ w2b, const float* __restrict__ b2b,
    const int* __restrict__ cols,
    float* __restrict__ g1, float* __restrict__ g2,
    float* __restrict__ deg1, float* __restrict__ deg2, int E)
{
    __shared__ float s1[16 * 128];
    __shared__ float s2[16 * 128];
    __shared__ float sb1[128], sb2[128], sv1[128], sv2[128];

    int tid = threadIdx.x;
    for (int i = tid; i < 2048; i += blockDim.x) { s1[i] = w1a[i]; s2[i] = w1b[i]; }
    if (tid < 128) {
        sb1[tid] = b1a[tid]; sb2[tid] = b1b[tid];
        sv1[tid] = w2a[tid]; sv2[tid] = w2b[tid];
    }
    __syncthreads();

    int e = blockIdx.x * blockDim.x + tid;
    if (e >= E) return;

    float a[16];
    const float4* p = (const float4*)(ea + (size_t)e * 16);
    float4 q0 = p[0], q1 = p[1], q2 = p[2], q3 = p[3];
    a[0]  = q0.x; a[1]  = q0.y; a[2]  = q0.z; a[3]  = q0.w;
    a[4]  = q1.x; a[5]  = q1.y; a[6]  = q1.z; a[7]  = q1.w;
    a[8]  = q2.x; a[9]  = q2.y; a[10] = q2.z; a[11] = q2.w;
    a[12] = q3.x; a[13] = q3.y; a[14] = q3.z; a[15] = q3.w;

    float acc1 = b2a[0];
    float acc2 = b2b[0];

    #pragma unroll 1
    for (int j = 0; j < 128; j += 4) {
        float4 h1 = *(const float4*)(sb1 + j);
        float4 h2 = *(const float4*)(sb2 + j);
        #pragma unroll
        for (int k = 0; k < 16; k++) {
            float4 w = *(const float4*)(s1 + k * 128 + j);
            h1.x = fmaf(a[k], w.x, h1.x);
            h1.y = fmaf(a[k], w.y, h1.y);
            h1.z = fmaf(a[k], w.z, h1.z);
            h1.w = fmaf(a[k], w.w, h1.w);
        }
        #pragma unroll
        for (int k = 0; k < 16; k++) {
            float4 w = *(const float4*)(s2 + k * 128 + j);
            h2.x = fmaf(a[k], w.x, h2.x);
            h2.y = fmaf(a[k], w.y, h2.y);
            h2.z = fmaf(a[k], w.z, h2.z);
            h2.w = fmaf(a[k], w.w, h2.w);
        }
        float4 v1 = *(const float4*)(sv1 + j);
        float4 v2 = *(const float4*)(sv2 + j);
        acc1 += fmaxf(h1.x, 0.0f) * v1.x + fmaxf(h1.y, 0.0f) * v1.y
              + fmaxf(h1.z, 0.0f) * v1.z + fmaxf(h1.w, 0.0f) * v1.w;
        acc2 += fmaxf(h2.x, 0.0f) * v2.x + fmaxf(h2.y, 0.0f) * v2.y
              + fmaxf(h2.z, 0.0f) * v2.z + fmaxf(h2.w, 0.0f) * v2.w;
    }

    float ga = 1.0f / (1.0f + expf(-acc1));
    float gb = 1.0f / (1.0f + expf(-acc2));
    g1[e] = ga;
    g2[e] = gb;
    int c = cols[e];
    atomicAdd(deg1 + c, ga);
    atomicAdd(deg2 + c, gb);
}

// ---------------------------------------------------------------------------
__global__ void rsqrt_kernel(float* d1, float* d2, int n) {
    int i = blockIdx.x * blockDim.x + threadIdx.x;
    if (i < n) {
        d1[i] = rsqrtf(d1[i]);   // deg >= 1 always (self-loop), no zero guard needed
        d2[i] = rsqrtf(d2[i]);
    }
}

// ---------------------------------------------------------------------------
// out[r][c] = sum_k act(X[r][k]) * W[k*128+c]. Warp handles 4 rows x 128 cols
// (each lane owns 4 consecutive cols). W read via LDG (64KB, L1-resident).
__global__ void gemm128_kernel(const float* __restrict__ X,
                               const float* __restrict__ W,
                               float* __restrict__ out, int n, int relu_in)
{
    __shared__ float xs[32 * 128];  // 8 warps x 4 rows
    int warp = threadIdx.x >> 5;
    int lane = threadIdx.x & 31;

    for (int base = blockIdx.x * 32; base < n; base += gridDim.x * 32) {
        int r0 = base + warp * 4;
        // stage 4 rows into shared
        #pragma unroll
        for (int i = 0; i < 4; i++) {
            int r = r0 + i;
            float4 v = make_float4(0.f, 0.f, 0.f, 0.f);
            if (r < n) v = ((const float4*)(X + (size_t)r * 128))[lane];
            if (relu_in) {
                v.x = fmaxf(v.x, 0.f); v.y = fmaxf(v.y, 0.f);
                v.z = fmaxf(v.z, 0.f); v.w = fmaxf(v.w, 0.f);
            }
            ((float4*)(xs + (warp * 4 + i) * 128))[lane] = v;
        }
        __syncwarp();

        float4 acc0 = make_float4(0.f, 0.f, 0.f, 0.f);
        float4 acc1 = acc0, acc2 = acc0, acc3 = acc0;
        const float* x0 = xs + warp * 4 * 128;

        #pragma unroll 16
        for (int k = 0; k < 128; k++) {
            float4 w = __ldg((const float4*)(W + k * 128) + lane);
            float xa = x0[k], xb = x0[128 + k], xc = x0[256 + k], xd = x0[384 + k];
            acc0.x = fmaf(xa, w.x, acc0.x); acc0.y = fmaf(xa, w.y, acc0.y);
            acc0.z = fmaf(xa, w.z, acc0.z); acc0.w = fmaf(xa, w.w, acc0.w);
            acc1.x = fmaf(xb, w.x, acc1.x); acc1.y = fmaf(xb, w.y, acc1.y);
            acc1.z = fmaf(xb, w.z, acc1.z); acc1.w = fmaf(xb, w.w, acc1.w);
            acc2.x = fmaf(xc, w.x, acc2.x); acc2.y = fmaf(xc, w.y, acc2.y);
            acc2.z = fmaf(xc, w.z, acc2.z); acc2.w = fmaf(xc, w.w, acc2.w);
            acc3.x = fmaf(xd, w.x, acc3.x); acc3.y = fmaf(xd, w.y, acc3.y);
            acc3.z = fmaf(xd, w.z, acc3.z); acc3.w = fmaf(xd, w.w, acc3.w);
        }

        if (r0 + 0 < n) ((float4*)(out + (size_t)(r0 + 0) * 128))[lane] = acc0;
        if (r0 + 1 < n) ((float4*)(out + (size_t)(r0 + 1) * 128))[lane] = acc1;
        if (r0 + 2 < n) ((float4*)(out + (size_t)(r0 + 2) * 128))[lane] = acc2;
        if (r0 + 3 < n) ((float4*)(out + (size_t)(r0 + 3) * 128))[lane] = acc3;
        __syncwarp();
    }
}

// ---------------------------------------------------------------------------
// Self-loop init: out[i][:] = dinv[i]^2 * h[i][:]  (also fully initializes out)
__global__ void selfloop_kernel(const float* __restrict__ h,
                                const float* __restrict__ dinv,
                                float* __restrict__ out, int n)
{
    int t = blockIdx.x * blockDim.x + threadIdx.x;  // one float4 per thread
    int total = n * 32;
    if (t >= total) return;
    int node = t >> 5;
    float w = dinv[node];
    w = w * w;
    float4 v = ((const float4*)h)[t];
    v.x *= w; v.y *= w; v.z *= w; v.w *= w;
    ((float4*)out)[t] = v;
}

// ---------------------------------------------------------------------------
// Scatter-aggregate: out[col] += (g * dinv[row] * dinv[col]) * h[row]
// One warp per edge, each lane owns 4 floats.
__global__ void scatter_kernel(const float* __restrict__ h,
                               float* __restrict__ out,
                               const int* __restrict__ rows,
                               const int* __restrict__ cols,
                               const float* __restrict__ g,
                               const float* __restrict__ dinv, int E)
{
    int e = blockIdx.x * 8 + (threadIdx.x >> 5);
    if (e >= E) return;
    int lane = threadIdx.x & 31;
    int r = __ldg(rows + e);
    int c = __ldg(cols + e);
    float w = __ldg(g + e) * __ldg(dinv + r) * __ldg(dinv + c);
    float4 v = ((const float4*)(h + (size_t)r * 128))[lane];
    float* o = out + (size_t)c * 128 + lane * 4;
    atomicAdd(o + 0, w * v.x);
    atomicAdd(o + 1, w * v.y);
    atomicAdd(o + 2, w * v.z);
    atomicAdd(o + 3, w * v.w);
}

// ---------------------------------------------------------------------------
extern "C" void kernel_launch(void* const* d_in, const int* in_sizes, int n_in,
                              void* d_out, int out_size)
{
    const float* x    = (const float*)d_in[0];
    const int*   ei   = (const int*)  d_in[1];
    const float* ea   = (const float*)d_in[2];
    const float* W1   = (const float*)d_in[3];
    const float* m1w1 = (const float*)d_in[4];
    const float* m1b1 = (const float*)d_in[5];
    const float* m1w2 = (const float*)d_in[6];
    const float* m1b2 = (const float*)d_in[7];
    const float* W2   = (const float*)d_in[8];
    const float* m2w1 = (const float*)d_in[9];
    const float* m2b1 = (const float*)d_in[10];
    const float* m2w2 = (const float*)d_in[11];
    const float* m2b2 = (const float*)d_in[12];
    float* out = (float*)d_out;

    int n = in_sizes[0] / 128;   // 100000
    int E = in_sizes[1] / 2;     // 1600000
    const int* rows = ei;
    const int* cols = ei + E;

    float *ph, *pagg, *pg1, *pg2, *pd1, *pd2;
    cudaGetSymbolAddress((void**)&ph,   g_h);
    cudaGetSymbolAddress((void**)&pagg, g_agg);
    cudaGetSymbolAddress((void**)&pg1,  g_g1);
    cudaGetSymbolAddress((void**)&pg2,  g_g2);
    cudaGetSymbolAddress((void**)&pd1,  g_d1);
    cudaGetSymbolAddress((void**)&pd2,  g_d2);

    // 1. deg = 1 (self loops)
    init_deg_kernel<<<(n + 255) / 256, 256>>>(pd1, pd2, n);
    // 2. gates for both layers + weighted in-degree accumulation
    gate_kernel<<<(E + 255) / 256, 256>>>(ea,
                                          m1w1, m1b1, m1w2, m1b2,
                                          m2w1, m2b1, m2w2, m2b2,
                                          cols, pg1, pg2, pd1, pd2, E);
    // 3. dinv = rsqrt(deg)
    rsqrt_kernel<<<(n + 255) / 256, 256>>>(pd1, pd2, n);

    // ---- Layer 1 ----
    gemm128_kernel<<<592, 256>>>(x, W1, ph, n, 0);
    selfloop_kernel<<<(n * 32 + 255) / 256, 256>>>(ph, pd1, pagg, n);
    scatter_kernel<<<(E + 7) / 8, 256>>>(ph, pagg, rows, cols, pg1, pd1, E);

    // ---- Layer 2 (relu fused into GEMM input) ----
    gemm128_kernel<<<592, 256>>>(pagg, W2, ph, n, 1);
    selfloop_kernel<<<(n * 32 + 255) / 256, 256>>>(ph, pd2, out, n);
    scatter_kernel<<<(E + 7) / 8, 256>>>(ph, out, rows, cols, pg2, pd2, E);
}

// round 2
// speedup vs baseline: 1.1978x; 1.1978x over previous
#include <cuda_runtime.h>
#include <math.h>

#define MAXN 100000
#define MAXE 1600000
#define NBLK 98          // ceil(MAXN/1024) for scans

// Scratch (__device__ globals; no allocation allowed)
__device__ float g_h[(size_t)MAXN * 128];    // h = x @ W (per layer)
__device__ float g_agg[(size_t)MAXN * 128];  // aggregated layer-1 output
__device__ float g_g1[MAXE];                 // edge gates layer 1
__device__ float g_g2[MAXE];                 // edge gates layer 2
__device__ float g_d1[MAXN];                 // deg -> rsqrt(deg) layer 1
__device__ float g_d2[MAXN];                 // deg -> rsqrt(deg) layer 2
__device__ int   g_cnt[MAXN];                // in-degree counts
__device__ int   g_cur[MAXN];                // placement cursors
__device__ int   g_base[MAXN];               // CSR base offsets
__device__ int   g_bsums[NBLK + 1];          // scan block sums
__device__ int   g_rowS[MAXE];               // CSR: source row per slot
__device__ float g_w1S[MAXE];                // CSR: combined weight layer 1
__device__ float g_w2S[MAXE];                // CSR: combined weight layer 2

// ---------------------------------------------------------------------------
__global__ void init_kernel(float* d1, float* d2, int* cnt, int* cur, int n) {
    int i = blockIdx.x * blockDim.x + threadIdx.x;
    if (i < n) { d1[i] = 1.0f; d2[i] = 1.0f; cnt[i] = 0; cur[i] = 0; }
}

// ---------------------------------------------------------------------------
// Edge gate MLPs for BOTH layers in one pass; also weighted in-degree and
// unweighted count histogram (for CSR).
__global__ void gate_kernel(
    const float* __restrict__ ea,
    const float* __restrict__ w1a, const float* __restrict__ b1a,
    const float* __restrict__ w2a, const float* __restrict__ b2a,
    const float* __restrict__ w1b, const float* __restrict__ b1b,
    const float* __restrict__ w2b, const float* __restrict__ b2b,
    const int* __restrict__ cols,
    float* __restrict__ g1, float* __restrict__ g2,
    float* __restrict__ deg1, float* __restrict__ deg2,
    int* __restrict__ cnt, int E)
{
    __shared__ float s1[16 * 128];
    __shared__ float s2[16 * 128];
    __shared__ float sb1[128], sb2[128], sv1[128], sv2[128];

    int tid = threadIdx.x;
    for (int i = tid; i < 2048; i += blockDim.x) { s1[i] = w1a[i]; s2[i] = w1b[i]; }
    if (tid < 128) {
        sb1[tid] = b1a[tid]; sb2[tid] = b1b[tid];
        sv1[tid] = w2a[tid]; sv2[tid] = w2b[tid];
    }
    __syncthreads();

    int e = blockIdx.x * blockDim.x + tid;
    if (e >= E) return;

    float a[16];
    const float4* p = (const float4*)(ea + (size_t)e * 16);
    float4 q0 = p[0], q1 = p[1], q2 = p[2], q3 = p[3];
    a[0]  = q0.x; a[1]  = q0.y; a[2]  = q0.z; a[3]  = q0.w;
    a[4]  = q1.x; a[5]  = q1.y; a[6]  = q1.z; a[7]  = q1.w;
    a[8]  = q2.x; a[9]  = q2.y; a[10] = q2.z; a[11] = q2.w;
    a[12] = q3.x; a[13] = q3.y; a[14] = q3.z; a[15] = q3.w;

    float acc1 = b2a[0];
    float acc2 = b2b[0];

    #pragma unroll 1
    for (int j = 0; j < 128; j += 4) {
        float4 h1 = *(const float4*)(sb1 + j);
        float4 h2 = *(const float4*)(sb2 + j);
        #pragma unroll
        for (int k = 0; k < 16; k++) {
            float4 w = *(const float4*)(s1 + k * 128 + j);
            h1.x = fmaf(a[k], w.x, h1.x);
            h1.y = fmaf(a[k], w.y, h1.y);
            h1.z = fmaf(a[k], w.z, h1.z);
            h1.w = fmaf(a[k], w.w, h1.w);
        }
        #pragma unroll
        for (int k = 0; k < 16; k++) {
            float4 w = *(const float4*)(s2 + k * 128 + j);
            h2.x = fmaf(a[k], w.x, h2.x);
            h2.y = fmaf(a[k], w.y, h2.y);
            h2.z = fmaf(a[k], w.z, h2.z);
            h2.w = fmaf(a[k], w.w, h2.w);
        }
        float4 v1 = *(const float4*)(sv1 + j);
        float4 v2 = *(const float4*)(sv2 + j);
        acc1 += fmaxf(h1.x, 0.0f) * v1.x + fmaxf(h1.y, 0.0f) * v1.y
              + fmaxf(h1.z, 0.0f) * v1.z + fmaxf(h1.w, 0.0f) * v1.w;
        acc2 += fmaxf(h2.x, 0.0f) * v2.x + fmaxf(h2.y, 0.0f) * v2.y
              + fmaxf(h2.z, 0.0f) * v2.z + fmaxf(h2.w, 0.0f) * v2.w;
    }

    float ga = 1.0f / (1.0f + expf(-acc1));
    float gb = 1.0f / (1.0f + expf(-acc2));
    g1[e] = ga;
    g2[e] = gb;
    int c = cols[e];
    atomicAdd(deg1 + c, ga);
    atomicAdd(deg2 + c, gb);
    atomicAdd(cnt + c, 1);
}

// ---------------------------------------------------------------------------
__global__ void rsqrt_kernel(float* d1, float* d2, int n) {
    int i = blockIdx.x * blockDim.x + threadIdx.x;
    if (i < n) {
        d1[i] = rsqrtf(d1[i]);
        d2[i] = rsqrtf(d2[i]);
    }
}

// ---------------------------------------------------------------------------
// Prefix sum over counts (3 kernels).
__global__ void scan_block_sums(const int* __restrict__ cnt, int* __restrict__ bsums, int n) {
    __shared__ int wsum[32];
    int i = blockIdx.x * 1024 + threadIdx.x;
    int v = (i < n) ? cnt[i] : 0;
    #pragma unroll
    for (int o = 16; o; o >>= 1) v += __shfl_down_sync(0xffffffffu, v, o);
    if ((threadIdx.x & 31) == 0) wsum[threadIdx.x >> 5] = v;
    __syncthreads();
    if (threadIdx.x < 32) {
        int s = wsum[threadIdx.x];
        #pragma unroll
        for (int o = 16; o; o >>= 1) s += __shfl_down_sync(0xffffffffu, s, o);
        if (threadIdx.x == 0) bsums[blockIdx.x] = s;
    }
}

__global__ void scan_bsums_excl(int* bsums, int nb) {
    if (threadIdx.x == 0 && blockIdx.x == 0) {
        int acc = 0;
        for (int i = 0; i < nb; i++) { int t = bsums[i]; bsums[i] = acc; acc += t; }
    }
}

__global__ void scan_final(const int* __restrict__ cnt, const int* __restrict__ bsums,
                           int* __restrict__ base, int n) {
    __shared__ int wsum[32];
    int i = blockIdx.x * 1024 + threadIdx.x;
    int v = (i < n) ? cnt[i] : 0;
    int lane = threadIdx.x & 31, w = threadIdx.x >> 5;
    int incl = v;
    #pragma unroll
    for (int o = 1; o < 32; o <<= 1) {
        int t = __shfl_up_sync(0xffffffffu, incl, o);
        if (lane >= o) incl += t;
    }
    if (lane == 31) wsum[w] = incl;
    __syncthreads();
    if (w == 0) {
        int s = wsum[lane];
        #pragma unroll
        for (int o = 1; o < 32; o <<= 1) {
            int t = __shfl_up_sync(0xffffffffu, s, o);
            if (lane >= o) s += t;
        }
        __syncwarp();
        wsum[lane] = s;
    }
    __syncthreads();
    int prev = (w == 0) ? 0 : wsum[w - 1];
    if (i < n) base[i] = incl - v + prev + bsums[blockIdx.x];
}

// ---------------------------------------------------------------------------
// CSR placement: slot per edge, write source row and combined weights for both
// layers (g * dinv[row] * dinv[col]).
__global__ void place_kernel(const int* __restrict__ rows, const int* __restrict__ cols,
                             const float* __restrict__ g1, const float* __restrict__ g2,
                             const float* __restrict__ d1, const float* __restrict__ d2,
                             const int* __restrict__ base, int* __restrict__ cur,
                             int* __restrict__ rowS, float* __restrict__ w1S,
                             float* __restrict__ w2S, int E)
{
    int e = blockIdx.x * blockDim.x + threadIdx.x;
    if (e >= E) return;
    int r = __ldg(rows + e);
    int c = __ldg(cols + e);
    int slot = __ldg(base + c) + atomicAdd(cur + c, 1);
    rowS[slot] = r;
    w1S[slot] = __ldg(g1 + e) * __ldg(d1 + r) * __ldg(d1 + c);
    w2S[slot] = __ldg(g2 + e) * __ldg(d2 + r) * __ldg(d2 + c);
}

// ---------------------------------------------------------------------------
// Dense GEMM: out[r][:] = act(X[r][:]) @ W, warp handles 4 rows.
__global__ void gemm128_kernel(const float* __restrict__ X,
                               const float* __restrict__ W,
                               float* __restrict__ out, int n, int relu_in)
{
    __shared__ float xs[32 * 128];
    int warp = threadIdx.x >> 5;
    int lane = threadIdx.x & 31;

    for (int base = blockIdx.x * 32; base < n; base += gridDim.x * 32) {
        int r0 = base + warp * 4;
        #pragma unroll
        for (int i = 0; i < 4; i++) {
            int r = r0 + i;
            float4 v = make_float4(0.f, 0.f, 0.f, 0.f);
            if (r < n) v = ((const float4*)(X + (size_t)r * 128))[lane];
            if (relu_in) {
                v.x = fmaxf(v.x, 0.f); v.y = fmaxf(v.y, 0.f);
                v.z = fmaxf(v.z, 0.f); v.w = fmaxf(v.w, 0.f);
            }
            ((float4*)(xs + (warp * 4 + i) * 128))[lane] = v;
        }
        __syncwarp();

        float4 acc0 = make_float4(0.f, 0.f, 0.f, 0.f);
        float4 acc1 = acc0, acc2 = acc0, acc3 = acc0;
        const float* x0 = xs + warp * 4 * 128;

        #pragma unroll 16
        for (int k = 0; k < 128; k++) {
            float4 w = __ldg((const float4*)(W + k * 128) + lane);
            float xa = x0[k], xb = x0[128 + k], xc = x0[256 + k], xd = x0[384 + k];
            acc0.x = fmaf(xa, w.x, acc0.x); acc0.y = fmaf(xa, w.y, acc0.y);
            acc0.z = fmaf(xa, w.z, acc0.z); acc0.w = fmaf(xa, w.w, acc0.w);
            acc1.x = fmaf(xb, w.x, acc1.x); acc1.y = fmaf(xb, w.y, acc1.y);
            acc1.z = fmaf(xb, w.z, acc1.z); acc1.w = fmaf(xb, w.w, acc1.w);
            acc2.x = fmaf(xc, w.x, acc2.x); acc2.y = fmaf(xc, w.y, acc2.y);
            acc2.z = fmaf(xc, w.z, acc2.z); acc2.w = fmaf(xc, w.w, acc2.w);
            acc3.x = fmaf(xd, w.x, acc3.x); acc3.y = fmaf(xd, w.y, acc3.y);
            acc3.z = fmaf(xd, w.z, acc3.z); acc3.w = fmaf(xd, w.w, acc3.w);
        }

        if (r0 + 0 < n) ((float4*)(out + (size_t)(r0 + 0) * 128))[lane] = acc0;
        if (r0 + 1 < n) ((float4*)(out + (size_t)(r0 + 1) * 128))[lane] = acc1;
        if (r0 + 2 < n) ((float4*)(out + (size_t)(r0 + 2) * 128))[lane] = acc2;
        if (r0 + 3 < n) ((float4*)(out + (size_t)(r0 + 3) * 128))[lane] = acc3;
        __syncwarp();
    }
}

// ---------------------------------------------------------------------------
// Gather-aggregate: one warp per node; self-loop fused into accumulator init.
// out[i] = dinv[i]^2 * h[i] + sum_{s in CSR(i)} wS[s] * h[rowS[s]]
__global__ void gather_kernel(const float* __restrict__ h,
                              const float* __restrict__ dinv,
                              const int* __restrict__ base,
                              const int* __restrict__ cnt,
                              const int* __restrict__ rowS,
                              const float* __restrict__ wS,
                              float* __restrict__ out, int n)
{
    int node = blockIdx.x * (blockDim.x >> 5) + (threadIdx.x >> 5);
    if (node >= n) return;
    int lane = threadIdx.x & 31;

    float di = __ldg(dinv + node);
    float w0 = di * di;
    float4 acc = __ldg((const float4*)(h + (size_t)node * 128) + lane);
    acc.x *= w0; acc.y *= w0; acc.z *= w0; acc.w *= w0;

    int s = __ldg(base + node);
    int end = s + __ldg(cnt + node);

    // 2-way unrolled to expose MLP
    for (; s + 2 <= end; s += 2) {
        int   r0 = __ldg(rowS + s),     r1 = __ldg(rowS + s + 1);
        float wa = __ldg(wS + s),       wb = __ldg(wS + s + 1);
        float4 v0 = __ldg((const float4*)(h + (size_t)r0 * 128) + lane);
        float4 v1 = __ldg((const float4*)(h + (size_t)r1 * 128) + lane);
        acc.x = fmaf(wa, v0.x, acc.x); acc.y = fmaf(wa, v0.y, acc.y);
        acc.z = fmaf(wa, v0.z, acc.z); acc.w = fmaf(wa, v0.w, acc.w);
        acc.x = fmaf(wb, v1.x, acc.x); acc.y = fmaf(wb, v1.y, acc.y);
        acc.z = fmaf(wb, v1.z, acc.z); acc.w = fmaf(wb, v1.w, acc.w);
    }
    if (s < end) {
        int   r0 = __ldg(rowS + s);
        float wa = __ldg(wS + s);
        float4 v0 = __ldg((const float4*)(h + (size_t)r0 * 128) + lane);
        acc.x = fmaf(wa, v0.x, acc.x); acc.y = fmaf(wa, v0.y, acc.y);
        acc.z = fmaf(wa, v0.z, acc.z); acc.w = fmaf(wa, v0.w, acc.w);
    }

    ((float4*)(out + (size_t)node * 128))[lane] = acc;
}

// ---------------------------------------------------------------------------
extern "C" void kernel_launch(void* const* d_in, const int* in_sizes, int n_in,
                              void* d_out, int out_size)
{
    const float* x    = (const float*)d_in[0];
    const int*   ei   = (const int*)  d_in[1];
    const float* ea   = (const float*)d_in[2];
    const float* W1   = (const float*)d_in[3];
    const float* m1w1 = (const float*)d_in[4];
    const float* m1b1 = (const float*)d_in[5];
    const float* m1w2 = (const float*)d_in[6];
    const float* m1b2 = (const float*)d_in[7];
    const float* W2   = (const float*)d_in[8];
    const float* m2w1 = (const float*)d_in[9];
    const float* m2b1 = (const float*)d_in[10];
    const float* m2w2 = (const float*)d_in[11];
    const float* m2b2 = (const float*)d_in[12];
    float* out = (float*)d_out;

    int n = in_sizes[0] / 128;   // 100000
    int E = in_sizes[1] / 2;     // 1600000
    const int* rows = ei;
    const int* cols = ei + E;
    int nblk = (n + 1023) / 1024;

    float *ph, *pagg, *pg1, *pg2, *pd1, *pd2, *pw1S, *pw2S;
    int *pcnt, *pcur, *pbase, *pbsums, *prowS;
    cudaGetSymbolAddress((void**)&ph,     g_h);
    cudaGetSymbolAddress((void**)&pagg,   g_agg);
    cudaGetSymbolAddress((void**)&pg1,    g_g1);
    cudaGetSymbolAddress((void**)&pg2,    g_g2);
    cudaGetSymbolAddress((void**)&pd1,    g_d1);
    cudaGetSymbolAddress((void**)&pd2,    g_d2);
    cudaGetSymbolAddress((void**)&pcnt,   g_cnt);
    cudaGetSymbolAddress((void**)&pcur,   g_cur);
    cudaGetSymbolAddress((void**)&pbase,  g_base);
    cudaGetSymbolAddress((void**)&pbsums, g_bsums);
    cudaGetSymbolAddress((void**)&prowS,  g_rowS);
    cudaGetSymbolAddress((void**)&pw1S,   g_w1S);
    cudaGetSymbolAddress((void**)&pw2S,   g_w2S);

    // Phase A: gates + degrees + counts
    init_kernel<<<(n + 255) / 256, 256>>>(pd1, pd2, pcnt, pcur, n);
    gate_kernel<<<(E + 255) / 256, 256>>>(ea,
                                          m1w1, m1b1, m1w2, m1b2,
                                          m2w1, m2b1, m2w2, m2b2,
                                          cols, pg1, pg2, pd1, pd2, pcnt, E);
    rsqrt_kernel<<<(n + 255) / 256, 256>>>(pd1, pd2, n);

    // Phase B: CSR build
    scan_block_sums<<<nblk, 1024>>>(pcnt, pbsums, n);
    scan_bsums_excl<<<1, 32>>>(pbsums, nblk);
    scan_final<<<nblk, 1024>>>(pcnt, pbsums, pbase, n);
    place_kernel<<<(E + 255) / 256, 256>>>(rows, cols, pg1, pg2, pd1, pd2,
                                           pbase, pcur, prowS, pw1S, pw2S, E);

    // Phase C: layer 1 (GEMM, then gather with fused self-loop)
    gemm128_kernel<<<592, 256>>>(x, W1, ph, n, 0);
    gather_kernel<<<(n + 7) / 8, 256>>>(ph, pd1, pbase, pcnt, prowS, pw1S, pagg, n);

    // Phase D: layer 2 (relu fused into GEMM input)
    gemm128_kernel<<<592, 256>>>(pagg, W2, ph, n, 1);
    gather_kernel<<<(n + 7) / 8, 256>>>(ph, pd2, pbase, pcnt, prowS, pw2S, out, n);
}

// round 3
// speedup vs baseline: 1.8386x; 1.5350x over previous
#include <cuda_runtime.h>
#include <math.h>

#define MAXN 100000
#define MAXE 1600000
#define NBLK 98          // ceil(MAXN/1024) for scans

// Scratch (__device__ globals; no allocation allowed)
__device__ float  g_h[(size_t)MAXN * 128];    // h = x @ W (per layer)
__device__ float  g_agg[(size_t)MAXN * 128];  // aggregated layer-1 output
__device__ float  g_g1[MAXE];                 // edge gates layer 1
__device__ float  g_g2[MAXE];                 // edge gates layer 2
__device__ float  g_d1[MAXN];                 // deg -> rsqrt(deg) layer 1
__device__ float  g_d2[MAXN];                 // deg -> rsqrt(deg) layer 2
__device__ int    g_cnt[MAXN];                // in-degree counts
__device__ int    g_cur[MAXN];                // placement cursors
__device__ int    g_base[MAXN];               // CSR base offsets
__device__ int    g_bsums[NBLK + 1];          // scan block sums
__device__ float4 g_edges[MAXE];              // CSR slot: {row(bits), w1, w2, 0}

// ---------------------------------------------------------------------------
__global__ void init_kernel(float* d1, float* d2, int* cnt, int* cur, int n) {
    int i = blockIdx.x * blockDim.x + threadIdx.x;
    if (i < n) { d1[i] = 1.0f; d2[i] = 1.0f; cnt[i] = 0; cur[i] = 0; }
}

// ---------------------------------------------------------------------------
// Edge gate MLPs for BOTH layers in one pass; also weighted in-degree and
// unweighted count histogram (for CSR).
__global__ void gate_kernel(
    const float* __restrict__ ea,
    const float* __restrict__ w1a, const float* __restrict__ b1a,
    const float* __restrict__ w2a, const float* __restrict__ b2a,
    const float* __restrict__ w1b, const float* __restrict__ b1b,
    const float* __restrict__ w2b, const float* __restrict__ b2b,
    const int* __restrict__ cols,
    float* __restrict__ g1, float* __restrict__ g2,
    float* __restrict__ deg1, float* __restrict__ deg2,
    int* __restrict__ cnt, int E)
{
    __shared__ float s1[16 * 128];
    __shared__ float s2[16 * 128];
    __shared__ float sb1[128], sb2[128], sv1[128], sv2[128];

    int tid = threadIdx.x;
    for (int i = tid; i < 2048; i += blockDim.x) { s1[i] = w1a[i]; s2[i] = w1b[i]; }
    if (tid < 128) {
        sb1[tid] = b1a[tid]; sb2[tid] = b1b[tid];
        sv1[tid] = w2a[tid]; sv2[tid] = w2b[tid];
    }
    __syncthreads();

    int e = blockIdx.x * blockDim.x + tid;
    if (e >= E) return;

    float a[16];
    const float4* p = (const float4*)(ea + (size_t)e * 16);
    float4 q0 = p[0], q1 = p[1], q2 = p[2], q3 = p[3];
    a[0]  = q0.x; a[1]  = q0.y; a[2]  = q0.z; a[3]  = q0.w;
    a[4]  = q1.x; a[5]  = q1.y; a[6]  = q1.z; a[7]  = q1.w;
    a[8]  = q2.x; a[9]  = q2.y; a[10] = q2.z; a[11] = q2.w;
    a[12] = q3.x; a[13] = q3.y; a[14] = q3.z; a[15] = q3.w;

    float acc1 = b2a[0];
    float acc2 = b2b[0];

    #pragma unroll 1
    for (int j = 0; j < 128; j += 4) {
        float4 h1 = *(const float4*)(sb1 + j);
        float4 h2 = *(const float4*)(sb2 + j);
        #pragma unroll
        for (int k = 0; k < 16; k++) {
            float4 w = *(const float4*)(s1 + k * 128 + j);
            h1.x = fmaf(a[k], w.x, h1.x);
            h1.y = fmaf(a[k], w.y, h1.y);
            h1.z = fmaf(a[k], w.z, h1.z);
            h1.w = fmaf(a[k], w.w, h1.w);
        }
        #pragma unroll
        for (int k = 0; k < 16; k++) {
            float4 w = *(const float4*)(s2 + k * 128 + j);
            h2.x = fmaf(a[k], w.x, h2.x);
            h2.y = fmaf(a[k], w.y, h2.y);
            h2.z = fmaf(a[k], w.z, h2.z);
            h2.w = fmaf(a[k], w.w, h2.w);
        }
        float4 v1 = *(const float4*)(sv1 + j);
        float4 v2 = *(const float4*)(sv2 + j);
        acc1 += fmaxf(h1.x, 0.0f) * v1.x + fmaxf(h1.y, 0.0f) * v1.y
              + fmaxf(h1.z, 0.0f) * v1.z + fmaxf(h1.w, 0.0f) * v1.w;
        acc2 += fmaxf(h2.x, 0.0f) * v2.x + fmaxf(h2.y, 0.0f) * v2.y
              + fmaxf(h2.z, 0.0f) * v2.z + fmaxf(h2.w, 0.0f) * v2.w;
    }

    float ga = 1.0f / (1.0f + expf(-acc1));
    float gb = 1.0f / (1.0f + expf(-acc2));
    g1[e] = ga;
    g2[e] = gb;
    int c = cols[e];
    atomicAdd(deg1 + c, ga);
    atomicAdd(deg2 + c, gb);
    atomicAdd(cnt + c, 1);
}

// ---------------------------------------------------------------------------
__global__ void rsqrt_kernel(float* d1, float* d2, int n) {
    int i = blockIdx.x * blockDim.x + threadIdx.x;
    if (i < n) {
        d1[i] = rsqrtf(d1[i]);
        d2[i] = rsqrtf(d2[i]);
    }
}

// ---------------------------------------------------------------------------
// Prefix sum over counts (3 kernels).
__global__ void scan_block_sums(const int* __restrict__ cnt, int* __restrict__ bsums, int n) {
    __shared__ int wsum[32];
    int i = blockIdx.x * 1024 + threadIdx.x;
    int v = (i < n) ? cnt[i] : 0;
    #pragma unroll
    for (int o = 16; o; o >>= 1) v += __shfl_down_sync(0xffffffffu, v, o);
    if ((threadIdx.x & 31) == 0) wsum[threadIdx.x >> 5] = v;
    __syncthreads();
    if (threadIdx.x < 32) {
        int s = wsum[threadIdx.x];
        #pragma unroll
        for (int o = 16; o; o >>= 1) s += __shfl_down_sync(0xffffffffu, s, o);
        if (threadIdx.x == 0) bsums[blockIdx.x] = s;
    }
}

__global__ void scan_bsums_excl(int* bsums, int nb) {
    if (threadIdx.x == 0 && blockIdx.x == 0) {
        int acc = 0;
        for (int i = 0; i < nb; i++) { int t = bsums[i]; bsums[i] = acc; acc += t; }
    }
}

__global__ void scan_final(const int* __restrict__ cnt, const int* __restrict__ bsums,
                           int* __restrict__ base, int n) {
    __shared__ int wsum[32];
    int i = blockIdx.x * 1024 + threadIdx.x;
    int v = (i < n) ? cnt[i] : 0;
    int lane = threadIdx.x & 31, w = threadIdx.x >> 5;
    int incl = v;
    #pragma unroll
    for (int o = 1; o < 32; o <<= 1) {
        int t = __shfl_up_sync(0xffffffffu, incl, o);
        if (lane >= o) incl += t;
    }
    if (lane == 31) wsum[w] = incl;
    __syncthreads();
    if (w == 0) {
        int s = wsum[lane];
        #pragma unroll
        for (int o = 1; o < 32; o <<= 1) {
            int t = __shfl_up_sync(0xffffffffu, s, o);
            if (lane >= o) s += t;
        }
        __syncwarp();
        wsum[lane] = s;
    }
    __syncthreads();
    int prev = (w == 0) ? 0 : wsum[w - 1];
    if (i < n) base[i] = incl - v + prev + bsums[blockIdx.x];
}

// ---------------------------------------------------------------------------
// CSR placement: one packed 16B record per edge slot:
//   {src_row (int bits), g*d1[r]*d1[c], g*d2[r]*d2[c], 0}
__global__ void place_kernel(const int* __restrict__ rows, const int* __restrict__ cols,
                             const float* __restrict__ g1, const float* __restrict__ g2,
                             const float* __restrict__ d1, const float* __restrict__ d2,
                             const int* __restrict__ base, int* __restrict__ cur,
                             float4* __restrict__ edges, int E)
{
    int e = blockIdx.x * blockDim.x + threadIdx.x;
    if (e >= E) return;
    int r = __ldg(rows + e);
    int c = __ldg(cols + e);
    int slot = __ldg(base + c) + atomicAdd(cur + c, 1);
    float4 rec;
    rec.x = __int_as_float(r);
    rec.y = __ldg(g1 + e) * __ldg(d1 + r) * __ldg(d1 + c);
    rec.z = __ldg(g2 + e) * __ldg(d2 + r) * __ldg(d2 + c);
    rec.w = 0.0f;
    edges[slot] = rec;
}

// ---------------------------------------------------------------------------
// Dense GEMM: out[r][:] = act(X[r][:]) @ W, warp handles 4 rows.
__global__ void gemm128_kernel(const float* __restrict__ X,
                               const float* __restrict__ W,
                               float* __restrict__ out, int n, int relu_in)
{
    __shared__ float xs[32 * 128];
    int warp = threadIdx.x >> 5;
    int lane = threadIdx.x & 31;

    for (int base = blockIdx.x * 32; base < n; base += gridDim.x * 32) {
        int r0 = base + warp * 4;
        #pragma unroll
        for (int i = 0; i < 4; i++) {
            int r = r0 + i;
            float4 v = make_float4(0.f, 0.f, 0.f, 0.f);
            if (r < n) v = ((const float4*)(X + (size_t)r * 128))[lane];
            if (relu_in) {
                v.x = fmaxf(v.x, 0.f); v.y = fmaxf(v.y, 0.f);
                v.z = fmaxf(v.z, 0.f); v.w = fmaxf(v.w, 0.f);
            }
            ((float4*)(xs + (warp * 4 + i) * 128))[lane] = v;
        }
        __syncwarp();

        float4 acc0 = make_float4(0.f, 0.f, 0.f, 0.f);
        float4 acc1 = acc0, acc2 = acc0, acc3 = acc0;
        const float* x0 = xs + warp * 4 * 128;

        #pragma unroll 16
        for (int k = 0; k < 128; k++) {
            float4 w = __ldg((const float4*)(W + k * 128) + lane);
            float xa = x0[k], xb = x0[128 + k], xc = x0[256 + k], xd = x0[384 + k];
            acc0.x = fmaf(xa, w.x, acc0.x); acc0.y = fmaf(xa, w.y, acc0.y);
            acc0.z = fmaf(xa, w.z, acc0.z); acc0.w = fmaf(xa, w.w, acc0.w);
            acc1.x = fmaf(xb, w.x, acc1.x); acc1.y = fmaf(xb, w.y, acc1.y);
            acc1.z = fmaf(xb, w.z, acc1.z); acc1.w = fmaf(xb, w.w, acc1.w);
            acc2.x = fmaf(xc, w.x, acc2.x); acc2.y = fmaf(xc, w.y, acc2.y);
            acc2.z = fmaf(xc, w.z, acc2.z); acc2.w = fmaf(xc, w.w, acc2.w);
            acc3.x = fmaf(xd, w.x, acc3.x); acc3.y = fmaf(xd, w.y, acc3.y);
            acc3.z = fmaf(xd, w.z, acc3.z); acc3.w = fmaf(xd, w.w, acc3.w);
        }

        if (r0 + 0 < n) ((float4*)(out + (size_t)(r0 + 0) * 128))[lane] = acc0;
        if (r0 + 1 < n) ((float4*)(out + (size_t)(r0 + 1) * 128))[lane] = acc1;
        if (r0 + 2 < n) ((float4*)(out + (size_t)(r0 + 2) * 128))[lane] = acc2;
        if (r0 + 3 < n) ((float4*)(out + (size_t)(r0 + 3) * 128))[lane] = acc3;
        __syncwarp();
    }
}

// ---------------------------------------------------------------------------
// Gather-aggregate: one warp per node; self-loop fused into accumulator init.
// out[i] = dinv[i]^2 * h[i] + sum_{s in CSR(i)} w[s] * h[row[s]]
// 4-way unrolled: 4 independent edge-record loads then 4 independent h-row
// gathers in flight (MLP >= 4 per warp) to cover ~250cyc L2 latency.
__global__ void __launch_bounds__(256)
gather_kernel(const float* __restrict__ h,
              const float* __restrict__ dinv,
              const int* __restrict__ base,
              const int* __restrict__ cnt,
              const float4* __restrict__ edges,
              float* __restrict__ out, int n, int sel)
{
    int node = blockIdx.x * (blockDim.x >> 5) + (threadIdx.x >> 5);
    if (node >= n) return;
    int lane = threadIdx.x & 31;

    float di = __ldg(dinv + node);
    float w0 = di * di;
    float4 acc = __ldg((const float4*)(h + (size_t)node * 128) + lane);
    acc.x *= w0; acc.y *= w0; acc.z *= w0; acc.w *= w0;

    int s = __ldg(base + node);
    int end = s + __ldg(cnt + node);

    for (; s + 4 <= end; s += 4) {
        float4 e0 = __ldg(edges + s);
        float4 e1 = __ldg(edges + s + 1);
        float4 e2 = __ldg(edges + s + 2);
        float4 e3 = __ldg(edges + s + 3);
        int r0 = __float_as_int(e0.x);
        int r1 = __float_as_int(e1.x);
        int r2 = __float_as_int(e2.x);
        int r3 = __float_as_int(e3.x);
        float w0_ = sel ? e0.z : e0.y;
        float w1_ = sel ? e1.z : e1.y;
        float w2_ = sel ? e2.z : e2.y;
        float w3_ = sel ? e3.z : e3.y;
        float4 v0 = __ldg((const float4*)(h + (size_t)r0 * 128) + lane);
        float4 v1 = __ldg((const float4*)(h + (size_t)r1 * 128) + lane);
        float4 v2 = __ldg((const float4*)(h + (size_t)r2 * 128) + lane);
        float4 v3 = __ldg((const float4*)(h + (size_t)r3 * 128) + lane);
        acc.x = fmaf(w0_, v0.x, acc.x); acc.y = fmaf(w0_, v0.y, acc.y);
        acc.z = fmaf(w0_, v0.z, acc.z); acc.w = fmaf(w0_, v0.w, acc.w);
        acc.x = fmaf(w1_, v1.x, acc.x); acc.y = fmaf(w1_, v1.y, acc.y);
        acc.z = fmaf(w1_, v1.z, acc.z); acc.w = fmaf(w1_, v1.w, acc.w);
        acc.x = fmaf(w2_, v2.x, acc.x); acc.y = fmaf(w2_, v2.y, acc.y);
        acc.z = fmaf(w2_, v2.z, acc.z); acc.w = fmaf(w2_, v2.w, acc.w);
        acc.x = fmaf(w3_, v3.x, acc.x); acc.y = fmaf(w3_, v3.y, acc.y);
        acc.z = fmaf(w3_, v3.z, acc.z); acc.w = fmaf(w3_, v3.w, acc.w);
    }
    for (; s < end; s++) {
        float4 e0 = __ldg(edges + s);
        int r0 = __float_as_int(e0.x);
        float wa = sel ? e0.z : e0.y;
        float4 v0 = __ldg((const float4*)(h + (size_t)r0 * 128) + lane);
        acc.x = fmaf(wa, v0.x, acc.x); acc.y = fmaf(wa, v0.y, acc.y);
        acc.z = fmaf(wa, v0.z, acc.z); acc.w = fmaf(wa, v0.w, acc.w);
    }

    ((float4*)(out + (size_t)node * 128))[lane] = acc;
}

// ---------------------------------------------------------------------------
extern "C" void kernel_launch(void* const* d_in, const int* in_sizes, int n_in,
                              void* d_out, int out_size)
{
    const float* x    = (const float*)d_in[0];
    const int*   ei   = (const int*)  d_in[1];
    const float* ea   = (const float*)d_in[2];
    const float* W1   = (const float*)d_in[3];
    const float* m1w1 = (const float*)d_in[4];
    const float* m1b1 = (const float*)d_in[5];
    const float* m1w2 = (const float*)d_in[6];
    const float* m1b2 = (const float*)d_in[7];
    const float* W2   = (const float*)d_in[8];
    const float* m2w1 = (const float*)d_in[9];
    const float* m2b1 = (const float*)d_in[10];
    const float* m2w2 = (const float*)d_in[11];
    const float* m2b2 = (const float*)d_in[12];
    float* out = (float*)d_out;

    int n = in_sizes[0] / 128;   // 100000
    int E = in_sizes[1] / 2;     // 1600000
    const int* rows = ei;
    const int* cols = ei + E;
    int nblk = (n + 1023) / 1024;

    float *ph, *pagg, *pg1, *pg2, *pd1, *pd2;
    float4* pedges;
    int *pcnt, *pcur, *pbase, *pbsums;
    cudaGetSymbolAddress((void**)&ph,     g_h);
    cudaGetSymbolAddress((void**)&pagg,   g_agg);
    cudaGetSymbolAddress((void**)&pg1,    g_g1);
    cudaGetSymbolAddress((void**)&pg2,    g_g2);
    cudaGetSymbolAddress((void**)&pd1,    g_d1);
    cudaGetSymbolAddress((void**)&pd2,    g_d2);
    cudaGetSymbolAddress((void**)&pcnt,   g_cnt);
    cudaGetSymbolAddress((void**)&pcur,   g_cur);
    cudaGetSymbolAddress((void**)&pbase,  g_base);
    cudaGetSymbolAddress((void**)&pbsums, g_bsums);
    cudaGetSymbolAddress((void**)&pedges, g_edges);

    // Phase A: gates + degrees + counts
    init_kernel<<<(n + 255) / 256, 256>>>(pd1, pd2, pcnt, pcur, n);
    gate_kernel<<<(E + 255) / 256, 256>>>(ea,
                                          m1w1, m1b1, m1w2, m1b2,
                                          m2w1, m2b1, m2w2, m2b2,
                                          cols, pg1, pg2, pd1, pd2, pcnt, E);
    rsqrt_kernel<<<(n + 255) / 256, 256>>>(pd1, pd2, n);

    // Phase B: CSR build
    scan_block_sums<<<nblk, 1024>>>(pcnt, pbsums, n);
    scan_bsums_excl<<<1, 32>>>(pbsums, nblk);
    scan_final<<<nblk, 1024>>>(pcnt, pbsums, pbase, n);
    place_kernel<<<(E + 255) / 256, 256>>>(rows, cols, pg1, pg2, pd1, pd2,
                                           pbase, pcur, pedges, E);

    // Phase C: layer 1 (GEMM, then gather with fused self-loop)
    gemm128_kernel<<<592, 256>>>(x, W1, ph, n, 0);
    gather_kernel<<<(n + 7) / 8, 256>>>(ph, pd1, pbase, pcnt, pedges, pagg, n, 0);

    // Phase D: layer 2 (relu fused into GEMM input)
    gemm128_kernel<<<592, 256>>>(pagg, W2, ph, n, 1);
    gather_kernel<<<(n + 7) / 8, 256>>>(ph, pd2, pbase, pcnt, pedges, out, n, 1);
}